// round 9
// baseline (speedup 1.0000x reference)
#include <cuda_runtime.h>

// HybridQuanvolutionFraudNet — exact constant folding (see R0 notes):
// log_softmax(logits) over a singleton axis is bitwise 0.0f for every sample,
// so the whole quanvolution + MLP pipeline is dead code. Output = 2048 float
// zeros. d_out is poisoned to 0xAA -> we must write it.
//
// R7: R6 showed graph MEMSET nodes replay ~0.7us SLOWER than a kernel node;
// reverted to the kernel-node form. Final geometry probe: minimum dispatch
// unit (1 CTA, 1 warp), 16 unrolled STG.128 per thread (issue-only, ~64 cyc
// total — negligible vs the fixed launch cost). Everything measured says the
// remaining ~4.6us is the per-launch floor.

__global__ __launch_bounds__(32, 1)
void hqfn_zero_1warp_kernel(float4* __restrict__ out) {
    const float4 z = make_float4(0.f, 0.f, 0.f, 0.f);
    const unsigned t = threadIdx.x;
#pragma unroll
    for (int k = 0; k < 16; ++k) {
        // 512 float4 = 16 chunks of 32; each warp store covers 512 B, coalesced.
        out[t + k * 32] = z;
    }
}

// Generic fallback for arbitrary out_size (never taken for this problem's
// fixed 2048-element output; keeps kernel_launch shape-safe).
__global__ void hqfn_zero_scalar_kernel(float* __restrict__ out, int n) {
    int i = blockIdx.x * blockDim.x + threadIdx.x;
    if (i < n) out[i] = 0.0f;
}

extern "C" void kernel_launch(void* const* d_in, const int* in_sizes, int n_in,
                              void* d_out, int out_size) {
    (void)d_in; (void)in_sizes; (void)n_in;
    if (out_size == 2048) {
        hqfn_zero_1warp_kernel<<<1, 32>>>((float4*)d_out);
    } else {
        int threads = 256;
        int blocks = (out_size + threads - 1) / threads;
        hqfn_zero_scalar_kernel<<<blocks, threads>>>((float*)d_out, out_size);
    }
}

// round 10
// speedup vs baseline: 1.1944x; 1.1944x over previous
#include <cuda_runtime.h>

// HybridQuanvolutionFraudNet — exact constant folding.
//
// The reference's final op is log_softmax(logits, axis=-1) on logits of shape
// [B, 1]. log_softmax over a singleton axis is identically 0.0f (x - x, with
// JAX's max-subtraction making it bitwise-exact zero) independent of every
// input, so the entire quanvolution + MLP pipeline is dead code. The exact
// output is 2048 float zeros; d_out is poisoned to 0xAA so we must write it.
//
// R9: full geometry sweep complete. Best measured config (kernel dur 3.30us,
// wall 4.61us) is 1 CTA x 512 threads, one STG.128 per thread:
//   - 1 CTA beats 8 CTAs (dispatch/drain tail ~0.6us),
//   - >=4 warps needed to overlap store issue with warp bring-up (1 warp with
//     16 serialized stores regressed to 3.55/5.50),
//   - graph MEMSET node replays ~0.7us SLOWER than a kernel node,
//   - all pipes ~0% -> pure per-launch fixed cost; this is the floor.

__global__ __launch_bounds__(512, 1)
void hqfn_zero_vec4_kernel(float4* __restrict__ out) {
    out[threadIdx.x] = make_float4(0.f, 0.f, 0.f, 0.f);
}

// Generic fallback for arbitrary out_size (never taken for this problem's
// fixed 2048-element output; keeps kernel_launch shape-safe).
__global__ void hqfn_zero_scalar_kernel(float* __restrict__ out, int n) {
    int i = blockIdx.x * blockDim.x + threadIdx.x;
    if (i < n) out[i] = 0.0f;
}

extern "C" void kernel_launch(void* const* d_in, const int* in_sizes, int n_in,
                              void* d_out, int out_size) {
    (void)d_in; (void)in_sizes; (void)n_in;
    if (out_size == 2048) {
        // 512 threads x float4 = 2048 floats, one block, one STG.128 each.
        hqfn_zero_vec4_kernel<<<1, 512>>>((float4*)d_out);
    } else {
        int threads = 256;
        int blocks = (out_size + threads - 1) / threads;
        hqfn_zero_scalar_kernel<<<blocks, threads>>>((float*)d_out, out_size);
    }
}